// round 3
// baseline (speedup 1.0000x reference)
#include <cuda_runtime.h>
#include <cstdint>

// Problem constants (from reference):
//   B=256, P=4096, H=W=512
// Inputs (metadata order):
//   d_in[0]: indices   int32  [B, P, 2]   (JAX x64 disabled: jnp.int64 request -> int32)
//   d_in[1]: num_valid int32  [B]
//   d_in[2]: feats     float32[B, P, 1]
// Output: float32 [B, H, W]

#define B_ 256
#define P_ 4096
#define H_ 512
#define W_ 512

__global__ __launch_bounds__(1024, 1)
void scatter_densify_kernel(const int* __restrict__ indices,
                            const int* __restrict__ num_valid,
                            const float* __restrict__ feats,
                            float* __restrict__ out)
{
    const int b = blockIdx.x;
    float* slice = out + (size_t)b * (H_ * W_);

    // Hoist the scalar load; latency hides under the fill loop.
    const int nv = num_valid[b];

    // ---- Phase 1: zero this batch's exclusive [H, W] slice ----
    // 512*512 floats = 65536 float4; 1024 threads -> 64 iterations.
    float4* s4 = reinterpret_cast<float4*>(slice);
    const float4 z = make_float4(0.f, 0.f, 0.f, 0.f);
    const int n4 = (H_ * W_) / 4;
    #pragma unroll 8
    for (int i = threadIdx.x; i < n4; i += 1024) {
        s4[i] = z;
    }
    __syncthreads();

    // ---- Phase 2: scatter-add valid points ----
    // indices for batch b: [P, 2] int32 -> load as int2 (8B per point)
    const int2* ib = reinterpret_cast<const int2*>(indices) + (size_t)b * P_;
    const float* fb = feats + (size_t)b * P_;

    for (int p = threadIdx.x; p < nv; p += 1024) {
        int2 rc = ib[p];
        int r = rc.x;
        int c = rc.y;
        if ((unsigned)r < H_ && (unsigned)c < W_) {
            atomicAdd(slice + r * W_ + c, fb[p]);
        }
    }
}

extern "C" void kernel_launch(void* const* d_in, const int* in_sizes, int n_in,
                              void* d_out, int out_size)
{
    const int*   indices = (const int*)d_in[0];
    const int*   nvalid  = (const int*)d_in[1];
    const float* feats   = (const float*)d_in[2];
    float*       out     = (float*)d_out;

    scatter_densify_kernel<<<B_, 1024>>>(indices, nvalid, feats, out);
}